// round 5
// baseline (speedup 1.0000x reference)
#include <cuda_runtime.h>
#include <cuda_bf16.h>

#define BB 32
#define NN 64
#define DD 64

// ---------------- device scratch (no allocations allowed) ----------------
__device__ float g_Q [BB*NN*DD];
__device__ float g_K1[BB*NN*DD];
__device__ float g_K2[BB*NN*DD];
__device__ float g_K3[BB*NN*DD];

// pairwise attention grams, pre-scaled by (-scale*log2(e)) so the main loop
// computes gate = 1/(1+exp2(sum)) with zero extra multiplies.
__device__ float g_qj [BB*NN*NN];   // [b][i][j] = Q[i]·K1[j]
__device__ float g_qk [BB*NN*NN];   // [b][i][k] = Q[i]·K2[k]
__device__ float g_ql [BB*NN*NN];   // [b][i][l] = Q[i]·K3[l]
__device__ float g_jkT[BB*NN*NN];   // [b][k][j] = K1[j]·K2[k]   (transposed!)
__device__ float g_jl [BB*NN*NN];   // [b][j][l] = K1[j]·K3[l]
__device__ float g_kl [BB*NN*NN];   // [b][k][l] = K2[k]·K3[l]

__device__ float g_feat[BB*NN];     // per-(b,anchor) raw sums

// ---------------- fast math helpers ----------------
__device__ __forceinline__ float ex2a(float x) {
    float y; asm("ex2.approx.ftz.f32 %0, %1;" : "=f"(y) : "f"(x)); return y;
}
__device__ __forceinline__ float rcpa(float x) {
    float y; asm("rcp.approx.ftz.f32 %0, %1;" : "=f"(y) : "f"(x)); return y;
}

// ---------------- kernel A1: dense layers (Q, K1, K2, K3) ----------------
__global__ void kA1(const float* __restrict__ pc,
                    const float* __restrict__ Wq,  const float* __restrict__ bq,
                    const float* __restrict__ Wk1, const float* __restrict__ bk1,
                    const float* __restrict__ Wk2, const float* __restrict__ bk2,
                    const float* __restrict__ Wk3, const float* __restrict__ bk3) {
    __shared__ float sP[NN*3];
    const int b = blockIdx.x;
    const int t = threadIdx.x;
    if (t < NN*3) sP[t] = pc[b*NN*3 + t];
    __syncthreads();
    for (int idx = t; idx < NN*DD; idx += blockDim.x) {
        const int n = idx >> 6, d = idx & 63;
        const float x = sP[n*3+0], y = sP[n*3+1], z = sP[n*3+2];
        const int o = b*NN*DD + idx;
        g_Q [o] = fmaf(x, Wq [d], fmaf(y, Wq [64+d], fmaf(z, Wq [128+d], bq [d])));
        g_K1[o] = fmaf(x, Wk1[d], fmaf(y, Wk1[64+d], fmaf(z, Wk1[128+d], bk1[d])));
        g_K2[o] = fmaf(x, Wk2[d], fmaf(y, Wk2[64+d], fmaf(z, Wk2[128+d], bk2[d])));
        g_K3[o] = fmaf(x, Wk3[d], fmaf(y, Wk3[64+d], fmaf(z, Wk3[128+d], bk3[d])));
    }
}

// ---------------- kernel A2: 6 gram matrices, pre-scaled ----------------
__global__ void kA2() {
    const int m = blockIdx.x;   // which gram
    const int b = blockIdx.y;   // batch
    const float* X; const float* Y; float* O;
    switch (m) {
        case 0:  X = g_Q;  Y = g_K1; O = g_qj;  break;
        case 1:  X = g_Q;  Y = g_K2; O = g_qk;  break;
        case 2:  X = g_Q;  Y = g_K3; O = g_ql;  break;
        case 3:  X = g_K2; Y = g_K1; O = g_jkT; break;  // gram(K2,K1)[k][j] = K1[j]·K2[k]
        case 4:  X = g_K1; Y = g_K3; O = g_jl;  break;
        default: X = g_K2; Y = g_K3; O = g_kl;  break;
    }
    __shared__ float sX[64][65];
    __shared__ float sY[64][65];
    const int t = threadIdx.x;
    for (int idx = t; idx < NN*DD; idx += blockDim.x) {
        sX[idx >> 6][idx & 63] = X[b*NN*DD + idx];
        sY[idx >> 6][idx & 63] = Y[b*NN*DD + idx];
    }
    __syncthreads();
    // scale = rsqrt(64) = 0.125; premultiply by -log2(e) for the exp2 sigmoid
    const float S2 = -0.125f * 1.4426950408889634f;
    for (int p = 0; p < 16; p++) {
        const int idx = t + p*256;
        const int r = idx >> 6, c = idx & 63;
        float s = 0.f;
        #pragma unroll
        for (int d = 0; d < DD; d++) s = fmaf(sX[r][d], sY[c][d], s);
        O[b*NN*NN + idx] = s * S2;
    }
}

// ---------------- kernel B: the 537M-element simplex loop ----------------
// One CTA per (batch, anchor i). Warp w owns k in [8w, 8w+8); lane holds
// l = lane and l = lane+32. cross(d_k, d_l) is hoisted out of the j-loop.
__global__ void __launch_bounds__(256) kB(const float* __restrict__ pc) {
    const int b = blockIdx.x >> 6;
    const int i = blockIdx.x & 63;
    const int t = threadIdx.x;
    const int lane = t & 31;
    const int w = t >> 5;

    __shared__ float s_jl[NN*NN];    // [j][l] with att_qj[i][j] folded into rows
    __shared__ float s_kl[NN*NN];    // [k][l] with att_qk[i][k], att_ql[i][l] folded
    __shared__ float sdx[NN], sdy[NN], sdz[NN];
    __shared__ float s_red[8];

    // displacements
    const float* pcb = pc + b*NN*3;
    const float pix = pcb[i*3+0], piy = pcb[i*3+1], piz = pcb[i*3+2];
    if (t < NN) {
        sdx[t] = pcb[t*3+0] - pix;
        sdy[t] = pcb[t*3+1] - piy;
        sdz[t] = pcb[t*3+2] - piz;
    }
    // load + fold attention matrices
    const float* gjl = g_jl + b*NN*NN;
    const float* gkl = g_kl + b*NN*NN;
    const float* gqj = g_qj + b*NN*NN + i*NN;
    const float* gqk = g_qk + b*NN*NN + i*NN;
    const float* gql = g_ql + b*NN*NN + i*NN;
    for (int idx = t; idx < NN*NN; idx += 256) {
        const int r = idx >> 6, c = idx & 63;
        s_jl[idx] = gjl[idx] + gqj[r];
        s_kl[idx] = gkl[idx] + gqk[r] + gql[c];
    }
    __syncthreads();

    const int l0 = lane, l1 = lane + 32;
    const float lx0 = sdx[l0], ly0 = sdy[l0], lz0 = sdz[l0];
    const float lx1 = sdx[l1], ly1 = sdy[l1], lz1 = sdz[l1];

    const float* gT = g_jkT + b*NN*NN;
    float acc0 = 0.f, acc1 = 0.f;

    for (int kk = 0; kk < 8; kk++) {
        const int k = w*8 + kk;
        // att_jk[:,k]: each lane holds 2 entries, broadcast via shfl in j-loop
        const float ajk0 = gT[k*64 + lane];        // j = lane
        const float ajk1 = gT[k*64 + lane + 32];   // j = lane+32

        const float kx = sdx[k], ky = sdy[k], kz = sdz[k];
        // cross(d_k, d_l), reused over all 64 j
        const float cx0 = ky*lz0 - kz*ly0;
        const float cy0 = kz*lx0 - kx*lz0;
        const float cz0 = kx*ly0 - ky*lx0;
        const float cx1 = ky*lz1 - kz*ly1;
        const float cy1 = kz*lx1 - kx*lz1;
        const float cz1 = kx*ly1 - ky*lx1;
        const float base0 = s_kl[k*64 + l0];
        const float base1 = s_kl[k*64 + l1];

        const float* sj0 = s_jl + l0;   // stride NN floats per j
        const float* sj1 = s_jl + l1;

        #pragma unroll 8
        for (int j = 0; j < 64; j++) {
            const float jx = sdx[j], jy = sdy[j], jz = sdz[j];  // uniform broadcast
            // att_jk[j,k]: broadcast from the lane that loaded it
            const float Au = __shfl_sync(0xffffffffu,
                                         (j < 32) ? ajk0 : ajk1, j & 31);
            const float d0 = fmaf(jx, cx0, fmaf(jy, cy0, jz*cz0));
            const float d1 = fmaf(jx, cx1, fmaf(jy, cy1, jz*cz1));
            const float e0 = Au + base0 + sj0[j*NN];
            const float e1 = Au + base1 + sj1[j*NN];
            // gate = sigmoid(energy) = 1/(1+exp2(pre-negated-scaled sum))
            const float g0 = rcpa(1.f + ex2a(e0));
            const float g1 = rcpa(1.f + ex2a(e1));
            acc0 = fmaf(d0*d0, g0, acc0);
            acc1 = fmaf(d1*d1, g1, acc1);
        }
    }

    float acc = acc0 + acc1;
    #pragma unroll
    for (int off = 16; off; off >>= 1)
        acc += __shfl_down_sync(0xffffffffu, acc, off);
    if (lane == 0) s_red[w] = acc;
    __syncthreads();
    if (t == 0) {
        float s = 0.f;
        #pragma unroll
        for (int q = 0; q < 8; q++) s += s_red[q];
        g_feat[blockIdx.x] = s;
    }
}

// ---------------- kernel C: pool + MLP head ----------------
// 64 threads: pair (b, half); each pair reduces 32 anchors, lane-adds, then
// the even thread of the pair runs the 32-wide MLP.
__global__ void kC(const float* __restrict__ W1, const float* __restrict__ b1,
                   const float* __restrict__ W2, const float* __restrict__ b2,
                   float* __restrict__ out) {
    const int t = threadIdx.x;       // 0..63
    const int b = t >> 1;            // batch
    const int h = t & 1;             // half
    float s = 0.f;
    #pragma unroll
    for (int i = 0; i < 32; i++) s += g_feat[b*NN + h*32 + i];
    s += __shfl_xor_sync(0xffffffffu, s, 1);   // pair-sum
    if (h == 0) {
        // /N^3 (agg) then mean over N anchors -> /64^4
        const float pooled = s * (1.0f / 16777216.0f);
        float o = b2[0];
        #pragma unroll
        for (int m = 0; m < 32; m++) {
            const float x  = fmaf(pooled, W1[m], b1[m]);
            const float x3 = x*x*x;
            const float th = tanhf(0.7978845608028654f * fmaf(0.044715f, x3, x));
            o = fmaf(0.5f * x * (1.f + th), W2[m], o);
        }
        out[b] = o;
    }
}

// ---------------- launcher ----------------
extern "C" void kernel_launch(void* const* d_in, const int* in_sizes, int n_in,
                              void* d_out, int out_size) {
    const float* pc  = (const float*)d_in[0];
    const float* Wq  = (const float*)d_in[1];
    const float* bq  = (const float*)d_in[2];
    const float* Wk1 = (const float*)d_in[3];
    const float* bk1 = (const float*)d_in[4];
    const float* Wk2 = (const float*)d_in[5];
    const float* bk2 = (const float*)d_in[6];
    const float* Wk3 = (const float*)d_in[7];
    const float* bk3 = (const float*)d_in[8];
    const float* W1  = (const float*)d_in[9];
    const float* b1  = (const float*)d_in[10];
    const float* W2  = (const float*)d_in[11];
    const float* b2  = (const float*)d_in[12];

    kA1<<<BB, 256>>>(pc, Wq, bq, Wk1, bk1, Wk2, bk2, Wk3, bk3);
    kA2<<<dim3(6, BB), 256>>>();
    kB<<<BB*NN, 256>>>(pc);
    kC<<<1, 64>>>(W1, b1, W2, b2, (float*)d_out);
}

// round 7
// speedup vs baseline: 1.2398x; 1.2398x over previous
#include <cuda_runtime.h>
#include <cuda_bf16.h>

#define BB 32
#define NN 64
#define DD 64

typedef unsigned long long ull;

// ---------------- device scratch (no allocations allowed) ----------------
__device__ float g_Q [BB*NN*DD];
__device__ float g_K1[BB*NN*DD];
__device__ float g_K2[BB*NN*DD];
__device__ float g_K3[BB*NN*DD];

// pairwise attention grams, pre-scaled by (+scale/2) so the main loop computes
// gate = 0.5*(1 + tanh(sum)) with zero extra multiplies.
__device__ float g_qj [BB*NN*NN];   // [b][i][j] = Q[i]·K1[j]
__device__ float g_qk [BB*NN*NN];   // [b][i][k] = Q[i]·K2[k]
__device__ float g_ql [BB*NN*NN];   // [b][i][l] = Q[i]·K3[l]
__device__ float g_jkT[BB*NN*NN];   // [b][k][j] = K1[j]·K2[k]   (transposed!)
__device__ float g_jl [BB*NN*NN];   // [b][j][l] = K1[j]·K3[l]
__device__ float g_kl [BB*NN*NN];   // [b][k][l] = K2[k]·K3[l]

__device__ float g_feat[BB*NN];     // per-(b,anchor) raw sums

// ---------------- packed f32x2 + fast-math helpers ----------------
__device__ __forceinline__ ull pk2(float lo, float hi) {
    ull r; asm("mov.b64 %0, {%1, %2};" : "=l"(r) : "f"(lo), "f"(hi)); return r;
}
__device__ __forceinline__ void upk2(float& lo, float& hi, ull v) {
    asm("mov.b64 {%0, %1}, %2;" : "=f"(lo), "=f"(hi) : "l"(v));
}
__device__ __forceinline__ ull fma2_(ull a, ull b, ull c) {
    ull r; asm("fma.rn.f32x2 %0, %1, %2, %3;" : "=l"(r) : "l"(a), "l"(b), "l"(c)); return r;
}
__device__ __forceinline__ ull add2_(ull a, ull b) {
    ull r; asm("add.rn.f32x2 %0, %1, %2;" : "=l"(r) : "l"(a), "l"(b)); return r;
}
__device__ __forceinline__ ull mul2_(ull a, ull b) {
    ull r; asm("mul.rn.f32x2 %0, %1, %2;" : "=l"(r) : "l"(a), "l"(b)); return r;
}
__device__ __forceinline__ float tanha(float x) {
    float y; asm("tanh.approx.f32 %0, %1;" : "=f"(y) : "f"(x)); return y;
}

// ---------------- kernel A1: dense layers (Q, K1, K2, K3) ----------------
__global__ void kA1(const float* __restrict__ pc,
                    const float* __restrict__ Wq,  const float* __restrict__ bq,
                    const float* __restrict__ Wk1, const float* __restrict__ bk1,
                    const float* __restrict__ Wk2, const float* __restrict__ bk2,
                    const float* __restrict__ Wk3, const float* __restrict__ bk3) {
    __shared__ float sP[NN*3];
    const int b = blockIdx.x;
    const int t = threadIdx.x;
    if (t < NN*3) sP[t] = pc[b*NN*3 + t];
    __syncthreads();
    for (int idx = t; idx < NN*DD; idx += blockDim.x) {
        const int n = idx >> 6, d = idx & 63;
        const float x = sP[n*3+0], y = sP[n*3+1], z = sP[n*3+2];
        const int o = b*NN*DD + idx;
        g_Q [o] = fmaf(x, Wq [d], fmaf(y, Wq [64+d], fmaf(z, Wq [128+d], bq [d])));
        g_K1[o] = fmaf(x, Wk1[d], fmaf(y, Wk1[64+d], fmaf(z, Wk1[128+d], bk1[d])));
        g_K2[o] = fmaf(x, Wk2[d], fmaf(y, Wk2[64+d], fmaf(z, Wk2[128+d], bk2[d])));
        g_K3[o] = fmaf(x, Wk3[d], fmaf(y, Wk3[64+d], fmaf(z, Wk3[128+d], bk3[d])));
    }
}

// ---------------- kernel A2: 6 gram matrices, pre-scaled ----------------
__global__ void kA2() {
    const int m = blockIdx.x;   // which gram
    const int b = blockIdx.y;   // batch
    const float* X; const float* Y; float* O;
    switch (m) {
        case 0:  X = g_Q;  Y = g_K1; O = g_qj;  break;
        case 1:  X = g_Q;  Y = g_K2; O = g_qk;  break;
        case 2:  X = g_Q;  Y = g_K3; O = g_ql;  break;
        case 3:  X = g_K2; Y = g_K1; O = g_jkT; break;  // gram(K2,K1)[k][j] = K1[j]·K2[k]
        case 4:  X = g_K1; Y = g_K3; O = g_jl;  break;
        default: X = g_K2; Y = g_K3; O = g_kl;  break;
    }
    __shared__ float sX[64][65];
    __shared__ float sY[64][65];
    const int t = threadIdx.x;
    for (int idx = t; idx < NN*DD; idx += blockDim.x) {
        sX[idx >> 6][idx & 63] = X[b*NN*DD + idx];
        sY[idx >> 6][idx & 63] = Y[b*NN*DD + idx];
    }
    __syncthreads();
    // scale = rsqrt(64) = 0.125; sigmoid(E)=0.5*(1+tanh(E/2)) -> prescale by 0.0625
    const float S2 = 0.0625f;
    for (int p = 0; p < 16; p++) {
        const int idx = t + p*256;
        const int r = idx >> 6, c = idx & 63;
        float s = 0.f;
        #pragma unroll
        for (int d = 0; d < DD; d++) s = fmaf(sX[r][d], sY[c][d], s);
        O[b*NN*NN + idx] = s * S2;
    }
}

// ---------------- kernel B: the 537M-element simplex loop (f32x2 packed) ----
// One CTA per (batch, anchor i). Warp w owns k in [8w, 8w+8); each lane packs
// its (l, l+32) pair into one f32x2 register. cross(d_k, d_l) hoisted per k.
// gate*det^2 = 0.5*d^2 + 0.5*d^2*tanh(E'); accumulate Sum(d^2) and Sum(d^2 t)
// in two packed accumulators, fold the 0.5 once at the end.
__global__ void __launch_bounds__(256) kB(const float* __restrict__ pc) {
    const int b = blockIdx.x >> 6;
    const int i = blockIdx.x & 63;
    const int t = threadIdx.x;
    const int lane = t & 31;
    const int w = t >> 5;

    __shared__ __align__(16) ull s_jl2[NN*32];   // [j][lane] = (jl+qj | l, l+32)
    __shared__ __align__(16) ull s_kl2[NN*32];   // [k][lane] = (kl+qk+ql | l, l+32)
    __shared__ __align__(16) ull sd2[NN][4];     // [n] = {(dx,dx),(dy,dy),(dz,dz),pad}
    __shared__ float sdx[NN], sdy[NN], sdz[NN];
    __shared__ ull  s_wjk2[8][64];               // per-warp duplicated att_jk column
    __shared__ float s_red[8];

    // displacements (scalar + duplicated-packed forms)
    const float* pcb = pc + b*NN*3;
    const float pix = pcb[i*3+0], piy = pcb[i*3+1], piz = pcb[i*3+2];
    if (t < NN) {
        const float dx = pcb[t*3+0] - pix;
        const float dy = pcb[t*3+1] - piy;
        const float dz = pcb[t*3+2] - piz;
        sdx[t] = dx; sdy[t] = dy; sdz[t] = dz;
        sd2[t][0] = pk2(dx, dx);
        sd2[t][1] = pk2(dy, dy);
        sd2[t][2] = pk2(dz, dz);
    }
    // fold attention matrices into packed pair layout
    const float* gjl = g_jl + b*NN*NN;
    const float* gkl = g_kl + b*NN*NN;
    const float* gqj = g_qj + b*NN*NN + i*NN;
    const float* gqk = g_qk + b*NN*NN + i*NN;
    const float* gql = g_ql + b*NN*NN + i*NN;
    for (int idx = t; idx < NN*32; idx += 256) {
        const int r = idx >> 5, l = idx & 31;
        const float qjr = gqj[r];
        s_jl2[idx] = pk2(gjl[r*64 + l] + qjr, gjl[r*64 + l + 32] + qjr);
        const float qkr = gqk[r];
        s_kl2[idx] = pk2(gkl[r*64 + l] + qkr + gql[l],
                         gkl[r*64 + l + 32] + qkr + gql[l + 32]);
    }
    __syncthreads();

    const int l0 = lane, l1 = lane + 32;
    const float lx0 = sdx[l0], ly0 = sdy[l0], lz0 = sdz[l0];
    const float lx1 = sdx[l1], ly1 = sdy[l1], lz1 = sdz[l1];

    const float* gT = g_jkT + b*NN*NN;
    ull acc_d = 0ull;   // bit pattern of (0.f, 0.f)
    ull acc_t = 0ull;

    for (int kk = 0; kk < 8; kk++) {
        const int k = w*8 + kk;
        // stage duplicated att_jk[:,k] column for uniform LDS.64 broadcast
        const float a0 = gT[k*64 + lane];
        const float a1 = gT[k*64 + lane + 32];
        s_wjk2[w][lane]      = pk2(a0, a0);
        s_wjk2[w][lane + 32] = pk2(a1, a1);
        __syncwarp();

        const float kx = sdx[k], ky = sdy[k], kz = sdz[k];
        // cross(d_k, d_l) scalar, packed once (reused over 64 j)
        const ull cx2 = pk2(ky*lz0 - kz*ly0, ky*lz1 - kz*ly1);
        const ull cy2 = pk2(kz*lx0 - kx*lz0, kz*lx1 - kx*lz1);
        const ull cz2 = pk2(kx*ly0 - ky*lx0, kx*ly1 - ky*lx1);
        const ull base2 = s_kl2[k*32 + lane];

        #pragma unroll 16
        for (int j = 0; j < 64; j++) {
            const ulonglong2 jxy = *reinterpret_cast<const ulonglong2*>(&sd2[j][0]);
            const ull jz2v = sd2[j][2];
            const ull Au2  = s_wjk2[w][j];
            const ull sjl  = s_jl2[j*32 + lane];
            const ull d2v  = fma2_(jxy.x, cx2, fma2_(jxy.y, cy2, mul2_(jz2v, cz2)));
            const ull e2   = add2_(add2_(Au2, base2), sjl);
            const ull dsq  = mul2_(d2v, d2v);
            acc_d = add2_(acc_d, dsq);
            float e0, e1; upk2(e0, e1, e2);
            const ull t2v = pk2(tanha(e0), tanha(e1));
            acc_t = fma2_(dsq, t2v, acc_t);
        }
        __syncwarp();   // protect s_wjk2 before next overwrite
    }

    float ad0, ad1, at0, at1;
    upk2(ad0, ad1, acc_d);
    upk2(at0, at1, acc_t);
    float acc = 0.5f * (ad0 + ad1 + at0 + at1);
    #pragma unroll
    for (int off = 16; off; off >>= 1)
        acc += __shfl_down_sync(0xffffffffu, acc, off);
    if (lane == 0) s_red[w] = acc;
    __syncthreads();
    if (t == 0) {
        float s = 0.f;
        #pragma unroll
        for (int q = 0; q < 8; q++) s += s_red[q];
        g_feat[blockIdx.x] = s;
    }
}

// ---------------- kernel C: pool + MLP head ----------------
__global__ void kC(const float* __restrict__ W1, const float* __restrict__ b1,
                   const float* __restrict__ W2, const float* __restrict__ b2,
                   float* __restrict__ out) {
    const int t = threadIdx.x;       // 0..63
    const int b = t >> 1;            // batch
    const int h = t & 1;             // half
    float s = 0.f;
    #pragma unroll
    for (int i = 0; i < 32; i++) s += g_feat[b*NN + h*32 + i];
    s += __shfl_xor_sync(0xffffffffu, s, 1);   // pair-sum
    if (h == 0) {
        // /N^3 (agg) then mean over N anchors -> /64^4
        const float pooled = s * (1.0f / 16777216.0f);
        float o = b2[0];
        #pragma unroll
        for (int m = 0; m < 32; m++) {
            const float x  = fmaf(pooled, W1[m], b1[m]);
            const float x3 = x*x*x;
            const float th = tanhf(0.7978845608028654f * fmaf(0.044715f, x3, x));
            o = fmaf(0.5f * x * (1.f + th), W2[m], o);
        }
        out[b] = o;
    }
}

// ---------------- launcher ----------------
extern "C" void kernel_launch(void* const* d_in, const int* in_sizes, int n_in,
                              void* d_out, int out_size) {
    const float* pc  = (const float*)d_in[0];
    const float* Wq  = (const float*)d_in[1];
    const float* bq  = (const float*)d_in[2];
    const float* Wk1 = (const float*)d_in[3];
    const float* bk1 = (const float*)d_in[4];
    const float* Wk2 = (const float*)d_in[5];
    const float* bk2 = (const float*)d_in[6];
    const float* Wk3 = (const float*)d_in[7];
    const float* bk3 = (const float*)d_in[8];
    const float* W1  = (const float*)d_in[9];
    const float* b1  = (const float*)d_in[10];
    const float* W2  = (const float*)d_in[11];
    const float* b2  = (const float*)d_in[12];

    kA1<<<BB, 256>>>(pc, Wq, bq, Wk1, bk1, Wk2, bk2, Wk3, bk3);
    kA2<<<dim3(6, BB), 256>>>();
    kB<<<BB*NN, 256>>>(pc);
    kC<<<1, 64>>>(W1, b1, W2, b2, (float*)d_out);
}